// round 1
// baseline (speedup 1.0000x reference)
#include <cuda_runtime.h>
#include <cooperative_groups.h>
#include <math.h>
#include <stdint.h>

namespace cg = cooperative_groups;

#define S_LEN 4096
#define D_DIM 300
#define HU    150
#define HH    300      // biLSTM concat dim
#define Z_DIM 600      // 4*HU
#define NSYN  4

// ---------------- scratch (static device memory; no allocation) ----------------
__device__ float g_emb[S_LEN * D_DIM];
__device__ float g_Zf[S_LEN * Z_DIM];
__device__ float g_Zb[S_LEN * Z_DIM];
__device__ float g_hidden[S_LEN * HH];
__device__ float g_Pout[S_LEN * HH];
__device__ float g_m[S_LEN * D_DIM];
__device__ float g_coeff[S_LEN];
__device__ float g_HHAT[2 * HH];

// ---------------- embedding gather ----------------
__global__ void k_gather(const int* __restrict__ sentence, const float* __restrict__ E) {
    int s = blockIdx.x;
    const float* src = E + (size_t)sentence[s] * D_DIM;
    float* dst = g_emb + (size_t)s * D_DIM;
    for (int d = threadIdx.x; d < D_DIM; d += blockDim.x) dst[d] = src[d];
}

// ---------------- fp32 tiled GEMM: C[M,N] = A[M,K] @ B[K,N] + bias ----------------
#define BM 64
#define BN 64
#define BK 16

template <int M, int N, int K, int REV>
__device__ __forceinline__ void gemm_body(const float* __restrict__ A,
                                          const float* __restrict__ B,
                                          const float* __restrict__ bias,
                                          float* __restrict__ C) {
    __shared__ float As[BM][BK + 1];
    __shared__ float Bs[BK][BN];
    const int tx = threadIdx.x, ty = threadIdx.y;
    const int tid = ty * 16 + tx;
    const int m0 = blockIdx.y * BM, n0 = blockIdx.x * BN;

    float acc[4][4];
#pragma unroll
    for (int i = 0; i < 4; i++)
#pragma unroll
        for (int j = 0; j < 4; j++) acc[i][j] = 0.f;

    for (int k0 = 0; k0 < K; k0 += BK) {
        // load A tile 64x16
#pragma unroll
        for (int l = 0; l < 4; l++) {
            int idx = tid + l * 256;
            int r = idx >> 4;
            int c = idx & 15;
            int gr = m0 + r;
            int gc = k0 + c;
            float v = 0.f;
            if (gc < K && gr < M) {
                int ar = REV ? (M - 1 - gr) : gr;
                v = A[(size_t)ar * K + gc];
            }
            As[r][c] = v;
        }
        // load B tile 16x64
#pragma unroll
        for (int l = 0; l < 4; l++) {
            int idx = tid + l * 256;
            int r = idx >> 6;
            int c = idx & 63;
            int gk = k0 + r, gn = n0 + c;
            float v = 0.f;
            if (gk < K && gn < N) v = B[(size_t)gk * N + gn];
            Bs[r][c] = v;
        }
        __syncthreads();
#pragma unroll
        for (int kk = 0; kk < BK; kk++) {
            float a0 = As[ty * 4 + 0][kk];
            float a1 = As[ty * 4 + 1][kk];
            float a2 = As[ty * 4 + 2][kk];
            float a3 = As[ty * 4 + 3][kk];
            float4 b4 = *reinterpret_cast<const float4*>(&Bs[kk][tx * 4]);
            acc[0][0] = fmaf(a0, b4.x, acc[0][0]); acc[0][1] = fmaf(a0, b4.y, acc[0][1]);
            acc[0][2] = fmaf(a0, b4.z, acc[0][2]); acc[0][3] = fmaf(a0, b4.w, acc[0][3]);
            acc[1][0] = fmaf(a1, b4.x, acc[1][0]); acc[1][1] = fmaf(a1, b4.y, acc[1][1]);
            acc[1][2] = fmaf(a1, b4.z, acc[1][2]); acc[1][3] = fmaf(a1, b4.w, acc[1][3]);
            acc[2][0] = fmaf(a2, b4.x, acc[2][0]); acc[2][1] = fmaf(a2, b4.y, acc[2][1]);
            acc[2][2] = fmaf(a2, b4.z, acc[2][2]); acc[2][3] = fmaf(a2, b4.w, acc[2][3]);
            acc[3][0] = fmaf(a3, b4.x, acc[3][0]); acc[3][1] = fmaf(a3, b4.y, acc[3][1]);
            acc[3][2] = fmaf(a3, b4.z, acc[3][2]); acc[3][3] = fmaf(a3, b4.w, acc[3][3]);
        }
        __syncthreads();
    }
#pragma unroll
    for (int i = 0; i < 4; i++) {
        int gr = m0 + ty * 4 + i;
        if (gr < M) {
#pragma unroll
            for (int j = 0; j < 4; j++) {
                int gn = n0 + tx * 4 + j;
                if (gn < N) C[(size_t)gr * N + gn] = acc[i][j] + bias[gn];
            }
        }
    }
}

__global__ void k_gemm_Zf(const float* __restrict__ W, const float* __restrict__ b) {
    gemm_body<S_LEN, Z_DIM, D_DIM, 0>(g_emb, W, b, g_Zf);
}
__global__ void k_gemm_Zb(const float* __restrict__ W, const float* __restrict__ b) {
    gemm_body<S_LEN, Z_DIM, D_DIM, 1>(g_emb, W, b, g_Zb);
}
__global__ void k_gemm_P(const float* __restrict__ W, const float* __restrict__ b) {
    gemm_body<S_LEN, HH, HH, 0>(g_hidden, W, b, g_Pout);
}

// ---------------- LSTM recurrence: 2 clusters (fwd/bwd) of 6 CTAs ----------------
#define GCL    6     // CTAs per cluster
#define UPC    25    // units per CTA (150/6)
#define OPC    100   // gate outputs per CTA (4*25)
#define TPO    4     // threads per output
#define KCH    40    // k-chunk per thread (4*40 >= 150), 16B aligned
#define LSTM_T 416   // 100*4 = 400 active, padded to 13 warps

__global__ __launch_bounds__(LSTM_T, 1) __cluster_dims__(GCL, 1, 1)
void k_lstm(const float* __restrict__ Uf, const float* __restrict__ Ub) {
    cg::cluster_group cluster = cg::this_cluster();
    const int rank = (int)cluster.block_rank();
    const int dir = blockIdx.x / GCL;  // 0 = fwd, 1 = bwd
    const float* __restrict__ Z = (dir == 0) ? g_Zf : g_Zb;
    const float* __restrict__ U = (dir == 0) ? Uf : Ub;

    __shared__ float h_sh[2][160];  // double buffered, padded (151..159 stay 0)
    __shared__ float z_sh[OPC];

    const int tid = threadIdx.x;
    const int o_local = tid >> 2;         // 0..103
    const int lg = tid & 3;               // lane within output group
    const bool active = (o_local < OPC);
    const int gate = o_local / UPC;       // 0..3 (i,f,g,o)
    const int u_loc = o_local - gate * UPC;
    int j = gate * HU + rank * UPC + u_loc;  // column in [0,600)
    if (!active) j = 0;
    const int k0 = lg * KCH;

    // U slice resident in registers
    float Ureg[KCH];
#pragma unroll
    for (int i = 0; i < KCH; i++) {
        int k = k0 + i;
        Ureg[i] = (active && k < HU) ? U[(size_t)k * Z_DIM + j] : 0.f;
    }

    for (int k = tid; k < 160; k += blockDim.x) { h_sh[0][k] = 0.f; h_sh[1][k] = 0.f; }

    float c = 0.f;
    float* peerA[GCL];
    float* peerB[GCL];
    if (tid < UPC) {
#pragma unroll
        for (int r = 0; r < GCL; r++) {
            peerA[r] = cluster.map_shared_rank(&h_sh[0][0], r);
            peerB[r] = cluster.map_shared_rank(&h_sh[1][0], r);
        }
    }
    const int slot = rank * UPC + tid;  // meaningful only for tid < UPC

    cluster.sync();

    // prefetch Z row for t=0
    float zcur = (active && lg == 0) ? Z[j] : 0.f;

    for (int t = 0; t < S_LEN; t++) {
        const float* hs = h_sh[t & 1];
        float acc = 0.f;
#pragma unroll
        for (int i = 0; i < KCH / 4; i++) {
            float4 hv = *reinterpret_cast<const float4*>(&hs[k0 + i * 4]);
            acc = fmaf(Ureg[4 * i + 0], hv.x, acc);
            acc = fmaf(Ureg[4 * i + 1], hv.y, acc);
            acc = fmaf(Ureg[4 * i + 2], hv.z, acc);
            acc = fmaf(Ureg[4 * i + 3], hv.w, acc);
        }
        acc += __shfl_xor_sync(0xffffffffu, acc, 1);
        acc += __shfl_xor_sync(0xffffffffu, acc, 2);
        if (active && lg == 0) {
            z_sh[o_local] = zcur + acc;
            if (t + 1 < S_LEN) zcur = __ldg(&Z[(size_t)(t + 1) * Z_DIM + j]);
        }
        __syncthreads();
        if (tid < UPC) {
            float zi = z_sh[tid];
            float zf = z_sh[UPC + tid];
            float zg = z_sh[2 * UPC + tid];
            float zo = z_sh[3 * UPC + tid];
            float ig = 1.f / (1.f + __expf(-zi));
            float fg = 1.f / (1.f + __expf(-zf));
            float gg = tanhf(zg);
            float og = 1.f / (1.f + __expf(-zo));
            c = fg * c + ig * gg;
            float h = og * tanhf(c);
            int nb = (t + 1) & 1;
#pragma unroll
            for (int r = 0; r < GCL; r++) {
                float* dst = nb ? peerB[r] : peerA[r];
                dst[slot] = h;
            }
            int s_out = (dir == 0) ? t : (S_LEN - 1 - t);
            g_hidden[(size_t)s_out * HH + dir * HU + slot] = h;
        }
        cluster.sync();
    }
}

// ---------------- primary attention (per word) + secondary attention coeff ----------------
__global__ void k_attn(const int* __restrict__ syn, const float* __restrict__ E,
                       const float* __restrict__ Ws, const float* __restrict__ bs) {
    int s = blockIdx.x;
    int tid = threadIdx.x;  // 128
    int warp = tid >> 5, lane = tid & 31;
    __shared__ float sc[NSYN];
    __shared__ int idx[NSYN];
    __shared__ float red[128];
    if (tid < NSYN) idx[tid] = syn[s * NSYN + tid];
    __syncthreads();
    {
        const float* sy = E + (size_t)idx[warp] * D_DIM;
        const float* po = g_Pout + (size_t)s * HH;
        float d0 = 0.f;
        for (int d = lane; d < D_DIM; d += 32) d0 = fmaf(po[d], sy[d], d0);
#pragma unroll
        for (int o = 16; o; o >>= 1) d0 += __shfl_xor_sync(0xffffffffu, d0, o);
        if (lane == 0) sc[warp] = __expf(d0);
    }
    __syncthreads();
    const float* e0 = E + (size_t)idx[0] * D_DIM;
    const float* e1 = E + (size_t)idx[1] * D_DIM;
    const float* e2 = E + (size_t)idx[2] * D_DIM;
    const float* e3 = E + (size_t)idx[3] * D_DIM;
    float s0 = sc[0], s1 = sc[1], s2 = sc[2], s3 = sc[3];
    float ca = 0.f;
    for (int d = tid; d < D_DIM; d += 128) {
        float md = s0 * e0[d] + s1 * e1[d] + s2 * e2[d] + s3 * e3[d];
        g_m[(size_t)s * D_DIM + d] = md;
        ca = fmaf(md, Ws[HH + d], ca);
        ca = fmaf(g_hidden[(size_t)s * HH + d], Ws[d], ca);
    }
    red[tid] = ca;
    __syncthreads();
    for (int o = 64; o; o >>= 1) {
        if (tid < o) red[tid] += red[tid + o];
        __syncthreads();
    }
    if (tid == 0) g_coeff[s] = __expf(tanhf(red[0] + bs[0]));
}

// ---------------- H_HAT[j] = sum_s coeff[s] * h_hats[s][j] ----------------
__global__ void k_hhat() {
    int jj = blockIdx.x * blockDim.x + threadIdx.x;
    if (jj >= 2 * HH) return;
    const float* src = (jj < HH) ? (g_hidden + jj) : (g_m + (jj - HH));
    float acc = 0.f;
    for (int s = 0; s < S_LEN; s++) acc = fmaf(g_coeff[s], src[(size_t)s * HH], acc);
    g_HHAT[jj] = acc;
}

// ---------------- output heads ----------------
__global__ void k_heads(const float* __restrict__ We, const float* __restrict__ be,
                        const float* __restrict__ Wse, const float* __restrict__ bse,
                        float* __restrict__ out) {
    int tid = threadIdx.x;
    if (tid < 8) {
        float a = 0.f;
        for (int jj = 0; jj < 2 * HH; jj++) a = fmaf(g_HHAT[jj], We[jj * 8 + tid], a);
        out[tid] = a + be[tid];
    } else if (tid == 8) {
        float a = 0.f;
        for (int jj = 0; jj < 2 * HH; jj++) a = fmaf(g_HHAT[jj], Wse[jj], a);
        out[8] = a + bse[0];
    }
}

// ---------------- launch ----------------
extern "C" void kernel_launch(void* const* d_in, const int* in_sizes, int n_in,
                              void* d_out, int out_size) {
    const int* sentence = (const int*)d_in[0];
    const int* syn = (const int*)d_in[1];
    const float* E = (const float*)d_in[2];
    const float* W_f = (const float*)d_in[3];
    const float* U_f = (const float*)d_in[4];
    const float* b_f = (const float*)d_in[5];
    const float* W_b = (const float*)d_in[6];
    const float* U_b = (const float*)d_in[7];
    const float* b_b = (const float*)d_in[8];
    const float* W_p = (const float*)d_in[9];
    const float* b_p = (const float*)d_in[10];
    const float* W_s = (const float*)d_in[11];
    const float* b_s = (const float*)d_in[12];
    const float* W_emo = (const float*)d_in[13];
    const float* b_emo = (const float*)d_in[14];
    const float* W_sent = (const float*)d_in[15];
    const float* b_sent = (const float*)d_in[16];
    float* out = (float*)d_out;

    k_gather<<<S_LEN, 128>>>(sentence, E);

    dim3 blk(16, 16);
    dim3 gz((Z_DIM + BN - 1) / BN, (S_LEN + BM - 1) / BM);
    k_gemm_Zf<<<gz, blk>>>(W_f, b_f);
    k_gemm_Zb<<<gz, blk>>>(W_b, b_b);

    k_lstm<<<2 * GCL, LSTM_T>>>(U_f, U_b);

    dim3 gp((HH + BN - 1) / BN, (S_LEN + BM - 1) / BM);
    k_gemm_P<<<gp, blk>>>(W_p, b_p);

    k_attn<<<S_LEN, 128>>>(syn, E, W_s, b_s);
    k_hhat<<<(2 * HH + 127) / 128, 128>>>();
    k_heads<<<1, 32>>>(W_emo, b_emo, W_sent, b_sent, out);
}